// round 8
// baseline (speedup 1.0000x reference)
#include <cuda_runtime.h>
#include <cstdint>

// ---------------------------------------------------------------------------
// out[n] = m_left^T @ (x[n] * diag_scale) @ m_right, n = 0..8191 (64x64 each)
// Identity split for tf32 precision:
//   E_L^T = m_left^T - I,  E_R = m_right - I
//   Y   = Xs + Xs @ E_R ;  out = Y + E_L^T @ Y
// Cayley via truncated polynomial: Q = (I+2M+M^2)(I+M^2)(I+M^4), M = A/2.
// Setup fused into ONE kernel (2 blocks, one per side).
// ---------------------------------------------------------------------------

__device__ float g_ELT[4096];      // (m_left^T - I)[l][i]
__device__ float g_ER[4096];       // (m_right  - I)[j][r]

#define CST 68   // smem stride: conflict-free fragment access patterns

// ---------------------------------------------------------------------------
// 64x64 smem matmul, 256 threads, 4x4 register tiles. C = (addA? A:0) + A*B
// ---------------------------------------------------------------------------
__device__ __forceinline__ void mm64t(float* C, const float* A, const float* B,
                                      bool addA, int tid)
{
    int r0 = (tid >> 4) << 2, c0 = (tid & 15) << 2;
    float acc[4][4];
    #pragma unroll
    for (int i = 0; i < 4; i++) {
        if (addA) {
            float4 a4 = *(const float4*)&A[(r0 + i) * CST + c0];
            acc[i][0] = a4.x; acc[i][1] = a4.y; acc[i][2] = a4.z; acc[i][3] = a4.w;
        } else {
            acc[i][0] = acc[i][1] = acc[i][2] = acc[i][3] = 0.0f;
        }
    }
    #pragma unroll 4
    for (int k = 0; k < 64; k++) {
        float4 b4 = *(const float4*)&B[k * CST + c0];
        #pragma unroll
        for (int i = 0; i < 4; i++) {
            float a = A[(r0 + i) * CST + k];
            acc[i][0] += a * b4.x; acc[i][1] += a * b4.y;
            acc[i][2] += a * b4.z; acc[i][3] += a * b4.w;
        }
    }
    #pragma unroll
    for (int i = 0; i < 4; i++)
        *(float4*)&C[(r0 + i) * CST + c0] =
            make_float4(acc[i][0], acc[i][1], acc[i][2], acc[i][3]);
    __syncthreads();
}

// ---------------------------------------------------------------------------
// Fused setup: 2 blocks x 256 threads. Block 0 -> g_ELT, block 1 -> g_ER.
// Per block: two polynomial Cayleys (4 matmuls each) + diag-combine (1 matmul).
// ---------------------------------------------------------------------------
__global__ void __launch_bounds__(256) setup_kernel(
    const float* __restrict__ ul, const float* __restrict__ vl,
    const float* __restrict__ dl,
    const float* __restrict__ ur, const float* __restrict__ vr,
    const float* __restrict__ dr)
{
    extern __shared__ float cs[];
    float* B0 = cs;                 // M, later L
    float* B1 = cs + 64 * CST;      // m2, later Q (Qv)
    float* B2 = cs + 2 * 64 * CST;  // m4, later E
    float* B3 = cs + 3 * 64 * CST;  // T
    float* B4 = cs + 4 * 64 * CST;  // Qu
    int b = blockIdx.x, tid = threadIdx.x;
    const float* dg = b ? dr : dl;

    #pragma unroll 1
    for (int c = 0; c < 2; c++) {
        const float* src = b ? (c ? vr : ur) : (c ? vl : ul);
        // M = A/2,  A = tril(X,-1) - tril(X,-1)^T
        for (int idx = tid; idx < 4096; idx += 256) {
            int i = idx >> 6, j = idx & 63;
            float a = 0.0f;
            if (i > j)      a =  src[i * 64 + j];
            else if (i < j) a = -src[j * 64 + i];
            B0[i * CST + j] = 0.5f * a;
        }
        __syncthreads();

        mm64t(B1, B0, B0, false, tid);   // m2 = M*M
        mm64t(B2, B1, B1, false, tid);   // m4 = m2*m2

        #pragma unroll
        for (int s = 0; s < 4; s++) {    // L = I + 2M + m2 (over M)
            int q = tid + s * 256;
            int r = q >> 4, c0 = (q & 15) * 4;
            float4 m  = *(float4*)&B0[r * CST + c0];
            float4 m2 = *(float4*)&B1[r * CST + c0];
            float4 L = make_float4(2.0f * m.x + m2.x, 2.0f * m.y + m2.y,
                                   2.0f * m.z + m2.z, 2.0f * m.w + m2.w);
            if (r == c0)     L.x += 1.0f;
            if (r == c0 + 1) L.y += 1.0f;
            if (r == c0 + 2) L.z += 1.0f;
            if (r == c0 + 3) L.w += 1.0f;
            *(float4*)&B0[r * CST + c0] = L;
        }
        __syncthreads();

        mm64t(B3, B0, B1, true, tid);            // T = L + L*m2
        mm64t(c == 0 ? B4 : B1, B3, B2, true, tid); // Q = T + T*m4
    }

    // scale Qv rows by diag: B1[k][*] *= d[k]
    for (int idx = tid; idx < 4096; idx += 256)
        B1[(idx >> 6) * CST + (idx & 63)] *= dg[idx >> 6];
    __syncthreads();

    mm64t(B2, B4, B1, false, tid);   // m = Qu @ (d ⊙ Qv)

    if (b == 0) {
        // g_ELT[l][i] = m[i][l] - (i==l)
        for (int idx = tid; idx < 4096; idx += 256) {
            int l = idx >> 6, i = idx & 63;
            g_ELT[idx] = B2[i * CST + l] - (i == l ? 1.0f : 0.0f);
        }
    } else {
        // g_ER[j][r] = m[j][r] - (j==r)
        for (int idx = tid; idx < 4096; idx += 256) {
            int j = idx >> 6, r = idx & 63;
            g_ER[idx] = B2[j * CST + r] - (j == r ? 1.0f : 0.0f);
        }
    }
}

// ---------------------------------------------------------------------------
// Main batched transform: tf32 mma.m16n8k8.
// 2 warps per matrix (64x32 slabs), 4 matrices/block concurrent, 2 rounds.
// ---------------------------------------------------------------------------
__device__ __forceinline__ unsigned f2tf32(float f) {
    unsigned u;
    asm("cvt.rna.tf32.f32 %0, %1;" : "=r"(u) : "f"(f));
    return u;
}

__device__ __forceinline__ void mma_tf32(float c[4],
    unsigned a0, unsigned a1, unsigned a2, unsigned a3,
    unsigned b0, unsigned b1)
{
    asm volatile(
        "mma.sync.aligned.m16n8k8.row.col.f32.tf32.tf32.f32 "
        "{%0,%1,%2,%3}, {%4,%5,%6,%7}, {%8,%9}, {%0,%1,%2,%3};\n"
        : "+f"(c[0]), "+f"(c[1]), "+f"(c[2]), "+f"(c[3])
        : "r"(a0), "r"(a1), "r"(a2), "r"(a3), "r"(b0), "r"(b1));
}

__global__ void __launch_bounds__(256, 2) trans_kernel(
    const float* __restrict__ x, const float* __restrict__ dscale,
    float* __restrict__ out)
{
    extern __shared__ float sm[];
    float*    Xs   = sm;                                  // 4 matrices, 64xCST
    unsigned* sELT = (unsigned*)(sm + 4 * 64 * CST);      // E_L^T, tf32, row-major
    unsigned* sERt = sELT + 64 * CST;                     // E_R, tf32, TRANSPOSED

    int tid = threadIdx.x;
    int w = tid >> 5, lane = tid & 31, gi = lane >> 2, ti = lane & 3;
    int g  = w >> 1;          // matrix group 0..3 (2 warps each)
    int c0 = (w & 1) * 32;    // this warp's column half

    for (int idx = tid; idx < 4096; idx += 256) {
        int i = idx >> 6, j = idx & 63;
        sELT[i * CST + j] = f2tf32(g_ELT[idx]);
        sERt[j * CST + i] = f2tf32(g_ER[idx]);   // transposed: [n][k]
    }

    float4 dsq[4];
    #pragma unroll
    for (int t = 0; t < 4; t++) dsq[t] = ((const float4*)dscale)[tid + t * 256];

    int base = blockIdx.x * 8 * 4096;
    __syncthreads();

    // E_R B-fragments into registers (fixed for whole kernel)
    unsigned erf[8][4][2];
    #pragma unroll
    for (int kt = 0; kt < 8; kt++)
        #pragma unroll
        for (int nt = 0; nt < 4; nt++) {
            erf[kt][nt][0] = sERt[(c0 + 8 * nt + gi) * CST + kt * 8 + ti];
            erf[kt][nt][1] = sERt[(c0 + 8 * nt + gi) * CST + kt * 8 + ti + 4];
        }

    #pragma unroll 1
    for (int rnd = 0; rnd < 2; rnd++) {
        // ---- cooperative fill of 4 matrices (coalesced) ----
        const float4* xp = (const float4*)(x + base + rnd * 4 * 4096);
        #pragma unroll
        for (int m = 0; m < 4; m++) {
            float* X = Xs + m * 64 * CST;
            #pragma unroll
            for (int t = 0; t < 4; t++) {
                int q = tid + t * 256;
                float4 v = xp[m * 1024 + q];
                v.x *= dsq[t].x; v.y *= dsq[t].y;
                v.z *= dsq[t].z; v.w *= dsq[t].w;
                *(float4*)&X[(q >> 4) * CST + (q & 15) * 4] = v;
            }
        }
        __syncthreads();

        float*    X  = Xs + g * 64 * CST;
        unsigned* Yt = (unsigned*)X;         // transposed tf32 Y, own cols only
        int xb = base + (rnd * 4 + g) * 4096;

        // ---- acc preload = Xs at C-fragment positions (exact identity) ----
        float acc[4][4][4];
        #pragma unroll
        for (int mt = 0; mt < 4; mt++)
            #pragma unroll
            for (int nt = 0; nt < 4; nt++) {
                int r = 16 * mt + gi, col = c0 + 8 * nt + 2 * ti;
                acc[mt][nt][0] = X[r * CST + col];
                acc[mt][nt][1] = X[r * CST + col + 1];
                acc[mt][nt][2] = X[(r + 8) * CST + col];
                acc[mt][nt][3] = X[(r + 8) * CST + col + 1];
            }

        // ---- Stage 1: acc += Xs @ E_R ----
        #pragma unroll
        for (int kt = 0; kt < 8; kt++) {
            int k0 = kt * 8;
            #pragma unroll
            for (int mt = 0; mt < 4; mt++) {
                int r = 16 * mt + gi;
                unsigned a0 = f2tf32(X[r * CST + k0 + ti]);
                unsigned a1 = f2tf32(X[(r + 8) * CST + k0 + ti]);
                unsigned a2 = f2tf32(X[r * CST + k0 + ti + 4]);
                unsigned a3 = f2tf32(X[(r + 8) * CST + k0 + ti + 4]);
                #pragma unroll
                for (int nt = 0; nt < 4; nt++)
                    mma_tf32(acc[mt][nt], a0, a1, a2, a3,
                             erf[kt][nt][0], erf[kt][nt][1]);
            }
        }

        // ---- group barrier: both warps done reading X; then write Y ----
        asm volatile("bar.sync %0, 64;" :: "r"(g + 1));

        // write Y transposed+tf32 into own column slab (warp-private)
        #pragma unroll
        for (int mt = 0; mt < 4; mt++)
            #pragma unroll
            for (int nt = 0; nt < 4; nt++) {
                int r = 16 * mt + gi, col = c0 + 8 * nt + 2 * ti;
                Yt[col * CST + r]           = f2tf32(acc[mt][nt][0]);
                Yt[(col + 1) * CST + r]     = f2tf32(acc[mt][nt][1]);
                Yt[col * CST + r + 8]       = f2tf32(acc[mt][nt][2]);
                Yt[(col + 1) * CST + r + 8] = f2tf32(acc[mt][nt][3]);
            }
        __syncwarp();

        // ---- Stage 2: acc += E_L^T @ Y (B from own transposed Y) ----
        #pragma unroll
        for (int kt = 0; kt < 8; kt++) {
            int k0 = kt * 8;
            unsigned b[4][2];
            #pragma unroll
            for (int nt = 0; nt < 4; nt++) {
                b[nt][0] = Yt[(c0 + 8 * nt + gi) * CST + k0 + ti];
                b[nt][1] = Yt[(c0 + 8 * nt + gi) * CST + k0 + ti + 4];
            }
            #pragma unroll
            for (int mt = 0; mt < 4; mt++) {
                int r = 16 * mt + gi;
                unsigned a0 = sELT[r * CST + k0 + ti];
                unsigned a1 = sELT[(r + 8) * CST + k0 + ti];
                unsigned a2 = sELT[r * CST + k0 + ti + 4];
                unsigned a3 = sELT[(r + 8) * CST + k0 + ti + 4];
                #pragma unroll
                for (int nt = 0; nt < 4; nt++)
                    mma_tf32(acc[mt][nt], a0, a1, a2, a3, b[nt][0], b[nt][1]);
            }
        }

        // ---- store ----
        #pragma unroll
        for (int mt = 0; mt < 4; mt++)
            #pragma unroll
            for (int nt = 0; nt < 4; nt++) {
                int r = 16 * mt + gi, col = c0 + 8 * nt + 2 * ti;
                *(float2*)&out[xb + r * 64 + col] =
                    make_float2(acc[mt][nt][0], acc[mt][nt][1]);
                *(float2*)&out[xb + (r + 8) * 64 + col] =
                    make_float2(acc[mt][nt][2], acc[mt][nt][3]);
            }
        __syncthreads();   // Xs reused next round
    }
}

// ---------------------------------------------------------------------------
// Launch
// ---------------------------------------------------------------------------
extern "C" void kernel_launch(void* const* d_in, const int* in_sizes, int n_in,
                              void* d_out, int out_size)
{
    const float* x   = (const float*)d_in[0];
    const float* ul  = (const float*)d_in[1];
    const float* vl  = (const float*)d_in[2];
    const float* dl  = (const float*)d_in[3];
    const float* ur  = (const float*)d_in[4];
    const float* vr  = (const float*)d_in[5];
    const float* dr  = (const float*)d_in[6];
    const float* dsc = (const float*)d_in[7];
    float* out = (float*)d_out;

    static const int kSetupSmem = 5 * 64 * CST * (int)sizeof(float); // 87040
    cudaFuncSetAttribute(setup_kernel,
                         cudaFuncAttributeMaxDynamicSharedMemorySize, kSetupSmem);
    setup_kernel<<<2, 256, kSetupSmem>>>(ul, vl, dl, ur, vr, dr);

    static const int kSmem = 6 * 64 * CST * (int)sizeof(float);      // 104448
    cudaFuncSetAttribute(trans_kernel,
                         cudaFuncAttributeMaxDynamicSharedMemorySize, kSmem);
    trans_kernel<<<1024, 256, kSmem>>>(x, dsc, out);
}

// round 9
// speedup vs baseline: 1.1615x; 1.1615x over previous
#include <cuda_runtime.h>
#include <cstdint>

// ---------------------------------------------------------------------------
// out[n] = m_left^T @ (x[n] * diag_scale) @ m_right, n = 0..8191 (64x64 each)
// Identity split for tf32 precision:
//   E_L^T = m_left^T - I,  E_R = m_right - I
//   Y   = Xs + Xs @ E_R ;  out = Y + E_L^T @ Y
// Cayley via truncated polynomial: Q = (I+2M+M^2)(I+M^2)(I+M^4), M = A/2.
// ---------------------------------------------------------------------------

__device__ float g_Q[4 * 4096];    // [u_l, v_l, u_r, v_r]
__device__ float g_ELT[4096];      // (m_left^T - I)[l][i]
__device__ float g_ER[4096];       // (m_right  - I)[j][r]

#define CST 68   // smem stride: conflict-free fragment access patterns

// ---------------------------------------------------------------------------
// 64x64 smem matmul, 256 threads, 4x4 register tiles. C = (addA? A:0) + A*B
// ---------------------------------------------------------------------------
__device__ __forceinline__ void mm64t(float* C, const float* A, const float* B,
                                      bool addA, int tid)
{
    int r0 = (tid >> 4) << 2, c0 = (tid & 15) << 2;
    float acc[4][4];
    #pragma unroll
    for (int i = 0; i < 4; i++) {
        if (addA) {
            float4 a4 = *(const float4*)&A[(r0 + i) * CST + c0];
            acc[i][0] = a4.x; acc[i][1] = a4.y; acc[i][2] = a4.z; acc[i][3] = a4.w;
        } else {
            acc[i][0] = acc[i][1] = acc[i][2] = acc[i][3] = 0.0f;
        }
    }
    #pragma unroll 4
    for (int k = 0; k < 64; k++) {
        float4 b4 = *(const float4*)&B[k * CST + c0];
        #pragma unroll
        for (int i = 0; i < 4; i++) {
            float a = A[(r0 + i) * CST + k];
            acc[i][0] += a * b4.x; acc[i][1] += a * b4.y;
            acc[i][2] += a * b4.z; acc[i][3] += a * b4.w;
        }
    }
    #pragma unroll
    for (int i = 0; i < 4; i++)
        *(float4*)&C[(r0 + i) * CST + c0] =
            make_float4(acc[i][0], acc[i][1], acc[i][2], acc[i][3]);
    __syncthreads();
}

// ---------------------------------------------------------------------------
// Kernel 1: 4 blocks x 256 threads; one polynomial Cayley each -> g_Q
// ---------------------------------------------------------------------------
__global__ void __launch_bounds__(256) cayley_kernel(
    const float* __restrict__ ul, const float* __restrict__ vl,
    const float* __restrict__ ur, const float* __restrict__ vr)
{
    extern __shared__ float cs[];
    float* B0 = cs;                 // M, later L
    float* B1 = cs + 64 * CST;      // m2, later Q
    float* B2 = cs + 2 * 64 * CST;  // m4
    float* B3 = cs + 3 * 64 * CST;  // T
    const float* src = (blockIdx.x == 0) ? ul : (blockIdx.x == 1) ? vl
                     : (blockIdx.x == 2) ? ur : vr;
    int tid = threadIdx.x;

    for (int idx = tid; idx < 4096; idx += 256) {
        int i = idx >> 6, j = idx & 63;
        float a = 0.0f;
        if (i > j)      a =  src[i * 64 + j];
        else if (i < j) a = -src[j * 64 + i];
        B0[i * CST + j] = 0.5f * a;
    }
    __syncthreads();

    mm64t(B1, B0, B0, false, tid);   // m2 = M*M
    mm64t(B2, B1, B1, false, tid);   // m4 = m2*m2

    #pragma unroll
    for (int s = 0; s < 4; s++) {    // L = I + 2M + m2 (over M)
        int q = tid + s * 256;
        int r = q >> 4, c0 = (q & 15) * 4;
        float4 m  = *(float4*)&B0[r * CST + c0];
        float4 m2 = *(float4*)&B1[r * CST + c0];
        float4 L = make_float4(2.0f * m.x + m2.x, 2.0f * m.y + m2.y,
                               2.0f * m.z + m2.z, 2.0f * m.w + m2.w);
        if (r == c0)     L.x += 1.0f;
        if (r == c0 + 1) L.y += 1.0f;
        if (r == c0 + 2) L.z += 1.0f;
        if (r == c0 + 3) L.w += 1.0f;
        *(float4*)&B0[r * CST + c0] = L;
    }
    __syncthreads();

    mm64t(B3, B0, B1, true, tid);    // T = L + L*m2
    mm64t(B1, B3, B2, true, tid);    // Q = T + T*m4

    float* dst = g_Q + blockIdx.x * 4096;
    for (int idx = tid; idx < 4096; idx += 256)
        dst[idx] = B1[(idx >> 6) * CST + (idx & 63)];
}

// ---------------------------------------------------------------------------
// Kernel 2: 8 blocks x 256 threads. side = b>>2 (0: ELT, 1: ER),
// slab = b&3 -> 16 output rows of m = Qu @ diag(d) @ Qv.
// ---------------------------------------------------------------------------
__global__ void __launch_bounds__(256) combine_kernel(
    const float* __restrict__ dl, const float* __restrict__ dr)
{
    __shared__ float Qa[16 * CST], Qb[64 * CST];
    int b = blockIdx.x, tid = threadIdx.x;
    int side = b >> 2, slab = b & 3;
    const float* qu = g_Q + side * 2 * 4096;
    const float* qv = qu + 4096;
    const float* dg = side ? dr : dl;

    for (int idx = tid; idx < 1024; idx += 256) {
        int r = idx >> 6, k = idx & 63;
        Qa[r * CST + k] = qu[(slab * 16 + r) * 64 + k];
    }
    for (int idx = tid; idx < 4096; idx += 256) {
        int k = idx >> 6, j = idx & 63;
        Qb[k * CST + j] = qv[idx] * dg[k];
    }
    __syncthreads();

    int r16 = tid >> 4, c0 = (tid & 15) * 4;
    int i = slab * 16 + r16;
    float acc[4] = {0.f, 0.f, 0.f, 0.f};
    #pragma unroll 8
    for (int k = 0; k < 64; k++) {
        float a = Qa[r16 * CST + k];
        float4 b4 = *(const float4*)&Qb[k * CST + c0];
        acc[0] += a * b4.x; acc[1] += a * b4.y;
        acc[2] += a * b4.z; acc[3] += a * b4.w;
    }
    #pragma unroll
    for (int e = 0; e < 4; e++) {
        int j = c0 + e;
        float v = acc[e] - (i == j ? 1.0f : 0.0f);
        if (side == 0) g_ELT[j * 64 + i] = v;    // transposed
        else           g_ER [i * 64 + j] = v;
    }
}

// ---------------------------------------------------------------------------
// Main batched transform: tf32 mma.m16n8k8 (raw fp32 bits, HW truncates).
// 2 matrices/block concurrent, 4 warps per matrix (16-col slabs), 2 rounds.
// ---------------------------------------------------------------------------
__device__ __forceinline__ void mma_tf32(float c[4],
    unsigned a0, unsigned a1, unsigned a2, unsigned a3,
    unsigned b0, unsigned b1)
{
    asm volatile(
        "mma.sync.aligned.m16n8k8.row.col.f32.tf32.tf32.f32 "
        "{%0,%1,%2,%3}, {%4,%5,%6,%7}, {%8,%9}, {%0,%1,%2,%3};\n"
        : "+f"(c[0]), "+f"(c[1]), "+f"(c[2]), "+f"(c[3])
        : "r"(a0), "r"(a1), "r"(a2), "r"(a3), "r"(b0), "r"(b1));
}

__global__ void __launch_bounds__(256, 3) trans_kernel(
    const float* __restrict__ x, const float* __restrict__ dscale,
    float* __restrict__ out)
{
    extern __shared__ float sm[];
    float*    Xs   = sm;                                  // 2 matrices, 64xCST
    unsigned* sELT = (unsigned*)(sm + 2 * 64 * CST);      // E_L^T bits, row-major

    int tid = threadIdx.x;
    int w = tid >> 5, lane = tid & 31, gi = lane >> 2, ti = lane & 3;
    int g  = w >> 2;          // matrix 0/1 (4 warps each)
    int c0 = (w & 3) * 16;    // this warp's 16-col slab

    // E_L^T bits into smem
    const unsigned* gelt = (const unsigned*)g_ELT;
    for (int idx = tid; idx < 4096; idx += 256)
        sELT[(idx >> 6) * CST + (idx & 63)] = gelt[idx];

    // E_R B-fragments straight from gmem into registers (bits)
    const unsigned* ger = (const unsigned*)g_ER;
    unsigned erf[8][2][2];
    #pragma unroll
    for (int kt = 0; kt < 8; kt++)
        #pragma unroll
        for (int nt = 0; nt < 2; nt++) {
            erf[kt][nt][0] = ger[(kt * 8 + ti)     * 64 + c0 + 8 * nt + gi];
            erf[kt][nt][1] = ger[(kt * 8 + ti + 4) * 64 + c0 + 8 * nt + gi];
        }

    int base = blockIdx.x * 4 * 4096;
    const float4* dsp = (const float4*)dscale;
    __syncthreads();

    #pragma unroll 1
    for (int rnd = 0; rnd < 2; rnd++) {
        // ---- cooperative fill of 2 matrices (coalesced, diag-scaled) ----
        const float4* xp = (const float4*)(x + base + rnd * 2 * 4096);
        #pragma unroll
        for (int m = 0; m < 2; m++) {
            float* X = Xs + m * 64 * CST;
            #pragma unroll
            for (int t = 0; t < 4; t++) {
                int q = tid + t * 256;
                float4 v = xp[m * 1024 + q];
                float4 d = __ldg(&dsp[q]);
                v.x *= d.x; v.y *= d.y; v.z *= d.z; v.w *= d.w;
                *(float4*)&X[(q >> 4) * CST + (q & 15) * 4] = v;
            }
        }
        __syncthreads();

        float*    X  = Xs + g * 64 * CST;
        unsigned* Xb = (unsigned*)X;
        unsigned* Yt = (unsigned*)X;         // Y bits, transposed, own cols
        int xb = base + (rnd * 2 + g) * 4096;

        // ---- acc preload = Xs at C positions (exact fp32 identity) ----
        float acc[4][2][4];
        #pragma unroll
        for (int mt = 0; mt < 4; mt++)
            #pragma unroll
            for (int nt = 0; nt < 2; nt++) {
                int r = 16 * mt + gi, col = c0 + 8 * nt + 2 * ti;
                float2 v0 = *(float2*)&X[r * CST + col];
                float2 v1 = *(float2*)&X[(r + 8) * CST + col];
                acc[mt][nt][0] = v0.x; acc[mt][nt][1] = v0.y;
                acc[mt][nt][2] = v1.x; acc[mt][nt][3] = v1.y;
            }

        // ---- Stage 1: acc += Xs @ E_R ----
        #pragma unroll
        for (int kt = 0; kt < 8; kt++) {
            int k0 = kt * 8;
            #pragma unroll
            for (int mt = 0; mt < 4; mt++) {
                int r = 16 * mt + gi;
                unsigned a0 = Xb[r * CST + k0 + ti];
                unsigned a1 = Xb[(r + 8) * CST + k0 + ti];
                unsigned a2 = Xb[r * CST + k0 + ti + 4];
                unsigned a3 = Xb[(r + 8) * CST + k0 + ti + 4];
                #pragma unroll
                for (int nt = 0; nt < 2; nt++)
                    mma_tf32(acc[mt][nt], a0, a1, a2, a3,
                             erf[kt][nt][0], erf[kt][nt][1]);
            }
        }

        // ---- group barrier: all 4 warps done reading X ----
        asm volatile("bar.sync %0, 128;" :: "r"(g + 1));

        // write Y bits transposed into own column slab (warp-private)
        #pragma unroll
        for (int mt = 0; mt < 4; mt++)
            #pragma unroll
            for (int nt = 0; nt < 2; nt++) {
                int r = 16 * mt + gi, col = c0 + 8 * nt + 2 * ti;
                Yt[col * CST + r]           = __float_as_uint(acc[mt][nt][0]);
                Yt[(col + 1) * CST + r]     = __float_as_uint(acc[mt][nt][1]);
                Yt[col * CST + r + 8]       = __float_as_uint(acc[mt][nt][2]);
                Yt[(col + 1) * CST + r + 8] = __float_as_uint(acc[mt][nt][3]);
            }
        __syncwarp();

        // ---- Stage 2: acc += E_L^T @ Y (B from own transposed Y) ----
        #pragma unroll
        for (int kt = 0; kt < 8; kt++) {
            int k0 = kt * 8;
            unsigned b[2][2];
            #pragma unroll
            for (int nt = 0; nt < 2; nt++) {
                b[nt][0] = Yt[(c0 + 8 * nt + gi) * CST + k0 + ti];
                b[nt][1] = Yt[(c0 + 8 * nt + gi) * CST + k0 + ti + 4];
            }
            #pragma unroll
            for (int mt = 0; mt < 4; mt++) {
                int r = 16 * mt + gi;
                unsigned a0 = sELT[r * CST + k0 + ti];
                unsigned a1 = sELT[(r + 8) * CST + k0 + ti];
                unsigned a2 = sELT[r * CST + k0 + ti + 4];
                unsigned a3 = sELT[(r + 8) * CST + k0 + ti + 4];
                #pragma unroll
                for (int nt = 0; nt < 2; nt++)
                    mma_tf32(acc[mt][nt], a0, a1, a2, a3, b[nt][0], b[nt][1]);
            }
        }

        // ---- store ----
        #pragma unroll
        for (int mt = 0; mt < 4; mt++)
            #pragma unroll
            for (int nt = 0; nt < 2; nt++) {
                int r = 16 * mt + gi, col = c0 + 8 * nt + 2 * ti;
                *(float2*)&out[xb + r * 64 + col] =
                    make_float2(acc[mt][nt][0], acc[mt][nt][1]);
                *(float2*)&out[xb + (r + 8) * 64 + col] =
                    make_float2(acc[mt][nt][2], acc[mt][nt][3]);
            }
        __syncthreads();   // Xs reused next round
    }
}

// ---------------------------------------------------------------------------
// Launch
// ---------------------------------------------------------------------------
extern "C" void kernel_launch(void* const* d_in, const int* in_sizes, int n_in,
                              void* d_out, int out_size)
{
    const float* x   = (const float*)d_in[0];
    const float* ul  = (const float*)d_in[1];
    const float* vl  = (const float*)d_in[2];
    const float* dl  = (const float*)d_in[3];
    const float* ur  = (const float*)d_in[4];
    const float* vr  = (const float*)d_in[5];
    const float* dr  = (const float*)d_in[6];
    const float* dsc = (const float*)d_in[7];
    float* out = (float*)d_out;

    static const int kCaySmem = 4 * 64 * CST * (int)sizeof(float);   // 69632
    cudaFuncSetAttribute(cayley_kernel,
                         cudaFuncAttributeMaxDynamicSharedMemorySize, kCaySmem);
    cayley_kernel<<<4, 256, kCaySmem>>>(ul, vl, ur, vr);
    combine_kernel<<<8, 256>>>(dl, dr);

    static const int kSmem = 3 * 64 * CST * (int)sizeof(float);      // 52224
    cudaFuncSetAttribute(trans_kernel,
                         cudaFuncAttributeMaxDynamicSharedMemorySize, kSmem);
    trans_kernel<<<2048, 256, kSmem>>>(x, dsc, out);
}